// round 14
// baseline (speedup 1.0000x reference)
#include <cuda_runtime.h>
#include <cuda_bf16.h>
#include <cuda_fp16.h>
#include <cstdint>
#include <cstddef>

// ---------------- problem constants ----------------
#define BATCH 2
#define CIN   64
#define HH    256
#define WW    256
#define CI    16
#define KS    7
#define STR   4
#define PT    1
#define PLW   1
#define LHH   64
#define LWW   64
#define LL    4096          // LHH*LWW
#define DD    784           // CI*KS*KS
#define DDP   832           // DD padded to mult of 64 (fc K)
#define DOUT  196
#define DOUTP 256           // DOUT padded to mult of 64

// ---------------- device scratch ----------------
__device__ __align__(16) float g_b1 [BATCH*CI*HH*WW];                 // 8 MB
__device__ __align__(16) float g_b2 [BATCH*CI*HH*WW];                 // 8 MB
__device__ __align__(16) __nv_bfloat16 g_wi_h [BATCH*LL*DDP];         // [b][l][832] pad->0
__device__ __align__(16) __nv_bfloat16 g_pit_h[BATCH*DD*LL];          // [b][d][l]
__device__ __align__(16) __nv_bfloat16 g_w1h[DOUT*DDP];
__device__ __align__(16) __nv_bfloat16 g_w2h[DOUT*DDP];
__device__ __align__(16) __nv_bfloat16 g_wif_h[BATCH*LL*DOUTP];
__device__ __align__(16) __nv_bfloat16 g_xif_h[BATCH*LL*DOUTP];
__device__ __align__(16) float g_thr [BATCH*LL];
__device__ __align__(16) float g_bias[BATCH*LL];
__device__ __align__(16) __half g_attn[(size_t)BATCH*LL*LL];          // 67 MB fp16 scores
__device__ __align__(16) __nv_bfloat16 g_attnh[(size_t)BATCH*LL*LL];  // 67 MB bf16 attn
__device__ __align__(16) float g_agg[BATCH*LL*DD];                    // 25.7 MB

// ---------------- packed f32x2 helpers ----------------
__device__ __forceinline__ void fma2(unsigned long long& a, unsigned long long w,
                                     unsigned long long v)
{
    asm("fma.rn.f32x2 %0, %1, %2, %0;" : "+l"(a) : "l"(w), "l"(v));
}
__device__ __forceinline__ unsigned long long pack2(float x, float y)
{
    unsigned long long r;
    asm("mov.b64 %0, {%1, %2};" : "=l"(r) : "f"(x), "f"(y));
    return r;
}
__device__ __forceinline__ void unpack2(float& x, float& y, unsigned long long a)
{
    asm("mov.b64 {%0, %1}, %2;" : "=f"(x), "=f"(y) : "l"(a));
}

// ---------------- K0: fc weights fp32 -> bf16 (padded) ----------------
__global__ void k_cvt_w(const float* __restrict__ w1, const float* __restrict__ w2)
{
    int idx = blockIdx.x * 256 + threadIdx.x;
    if (idx >= 2 * DOUT * DDP) return;
    int zz = idx / (DOUT * DDP);
    int r = (idx / DDP) % DOUT;
    int c = idx % DDP;
    const float* w = zz ? w2 : w1;
    __nv_bfloat16* o = zz ? g_w2h : g_w1h;
    float v = (c < DD) ? w[r * DD + c] : 0.f;
    o[idx - zz * DOUT * DDP] = __float2bfloat16(v);
}

// ---------------- K1: conv3x3 (b1) + conv1x1 (b2), exact fp32, f32x2 packed ----------------
__global__ __launch_bounds__(256) void k_conv(const float* __restrict__ bin,
                                              const float* __restrict__ gw,
                                              const float* __restrict__ gb,
                                              const float* __restrict__ tw,
                                              const float* __restrict__ tb)
{
    __shared__ unsigned long long sGw2[CIN * 9 * 8];   // [(ci*9+tap)*8+p] = (w[2p], w[2p+1])
    __shared__ unsigned long long sTw2[CIN * 8];       // [ci*8+p]
    __shared__ float sGb[CI], sTb[CI];
    int t = threadIdx.x;
    for (int i = t; i < CIN * 9 * 8; i += 256) {
        int ci = i / 72;
        int tap = (i / 8) % 9;
        int p = i & 7;
        sGw2[i] = pack2(gw[((2 * p) * CIN + ci) * 9 + tap],
                        gw[((2 * p + 1) * CIN + ci) * 9 + tap]);
    }
    for (int i = t; i < CIN * 8; i += 256) {
        int ci = i / 8;
        int p = i & 7;
        sTw2[i] = pack2(tw[(2 * p) * CIN + ci], tw[(2 * p + 1) * CIN + ci]);
    }
    if (t < CI) { sGb[t] = gb[t]; sTb[t] = tb[t]; }
    __syncthreads();

    int idx = blockIdx.x * 256 + t;
    int x = idx & 255;
    int y = (idx >> 8) & 255;
    int bb = idx >> 16;

    unsigned long long a1p[8], a2p[8];
#pragma unroll
    for (int p = 0; p < 8; p++) { a1p[p] = 0ull; a2p[p] = 0ull; }

    bool ym = y > 0, yP = y < HH - 1, xm = x > 0, xP = x < WW - 1;
    const float* base = bin + ((size_t)bb * CIN * HH + y) * WW + x;

    for (int ci = 0; ci < CIN; ci++) {
        const float* p = base + (size_t)ci * HH * WW;
        float v4 = p[0];
        float v0 = (ym && xm) ? p[-WW - 1] : 0.f;
        float v1 = ym ? p[-WW] : 0.f;
        float v2 = (ym && xP) ? p[-WW + 1] : 0.f;
        float v3 = xm ? p[-1] : 0.f;
        float v5 = xP ? p[1] : 0.f;
        float v6 = (yP && xm) ? p[WW - 1] : 0.f;
        float v7 = yP ? p[WW] : 0.f;
        float v8 = (yP && xP) ? p[WW + 1] : 0.f;
        unsigned long long vv[9];
        vv[0] = pack2(v0, v0); vv[1] = pack2(v1, v1); vv[2] = pack2(v2, v2);
        vv[3] = pack2(v3, v3); vv[4] = pack2(v4, v4); vv[5] = pack2(v5, v5);
        vv[6] = pack2(v6, v6); vv[7] = pack2(v7, v7); vv[8] = pack2(v8, v8);
        const unsigned long long* wg = sGw2 + ci * 72;
#pragma unroll
        for (int pp = 0; pp < 8; pp++) {
#pragma unroll
            for (int tap = 0; tap < 9; tap++)
                fma2(a1p[pp], wg[tap * 8 + pp], vv[tap]);
            fma2(a2p[pp], sTw2[ci * 8 + pp], vv[4]);
        }
    }
#pragma unroll
    for (int pp = 0; pp < 8; pp++) {
        float x0, x1, y0, y1;
        unpack2(x0, x1, a1p[pp]);
        unpack2(y0, y1, a2p[pp]);
        int co0 = 2 * pp, co1 = 2 * pp + 1;
        size_t off0 = ((size_t)(bb * CI + co0) * HH + y) * WW + x;
        size_t off1 = ((size_t)(bb * CI + co1) * HH + y) * WW + x;
        g_b1[off0] = x0 + sGb[co0];
        g_b1[off1] = x1 + sGb[co1];
        g_b2[off0] = y0 + sTb[co0];
        g_b2[off1] = y1 + sTb[co1];
    }
}

// ---------------- K2: thr / bias conv7x7 stride4 (4 patches / block) ----------------
__global__ __launch_bounds__(256) void k_thrbias(const float* __restrict__ bin,
                          const float* __restrict__ thw, const float* __restrict__ thb,
                          const float* __restrict__ biw, const float* __restrict__ bib)
{
    int t = threadIdx.x;
    int g = t >> 6;                      // patch group 0..3
    int ci = t & 63;
    int blk = blockIdx.x * 4 + g;        // b*LL + l
    int bb = blk >> 12;
    int l  = blk & (LL - 1);
    int lh = l >> 6, lw = l & 63;
    const float* src = bin + (size_t)(bb * CIN + ci) * HH * WW;
    float s1 = 0.f, s2 = 0.f;
    for (int r = 0; r < KS; r++) {
        int y = lh * STR + r - PT;
        if ((unsigned)y < HH) {
            for (int c = 0; c < KS; c++) {
                int x = lw * STR + c - PLW;
                if ((unsigned)x < WW) {
                    float v = src[y * WW + x];
                    s1 += v * thw[ci * 49 + r * 7 + c];
                    s2 += v * biw[ci * 49 + r * 7 + c];
                }
            }
        }
    }
    for (int o = 16; o; o >>= 1) {
        s1 += __shfl_xor_sync(0xffffffffu, s1, o);
        s2 += __shfl_xor_sync(0xffffffffu, s2, o);
    }
    __shared__ float r1[8], r2[8];
    if ((t & 31) == 0) { r1[t >> 5] = s1; r2[t >> 5] = s2; }
    __syncthreads();
    if ((t & 63) == 0) {
        int w0 = t >> 5;                 // = g*2
        g_thr [blk] = r1[w0] + r1[w0 + 1] + thb[0];
        g_bias[blk] = r2[w0] + r2[w0 + 1] + bib[0];
    }
}

// ---------------- K3a: wi patches (bf16 [b][l][832]), 2 elems/thread ----------------
__global__ void k_patch_wi()
{
    int idx = blockIdx.x * 256 + threadIdx.x;    // < BATCH*LL*DDP/2
    int d2 = idx % (DDP / 2);
    int bl = idx / (DDP / 2);
    int l = bl & (LL - 1);
    int bb = bl >> 12;
    int yb = (l >> 6) * STR - PT;
    int xb = (l & 63) * STR - PLW;
    __nv_bfloat162 v;
    float f[2] = {0.f, 0.f};
#pragma unroll
    for (int j = 0; j < 2; j++) {
        int d = d2 * 2 + j;
        if (d < DD) {
            int ci = d / 49;
            int rc = d % 49;
            int r = rc / 7, c = rc % 7;
            int y = yb + r, x = xb + c;
            if ((unsigned)y < HH && (unsigned)x < WW)
                f[j] = g_b1[((size_t)(bb * CI + ci) * HH + y) * WW + x];
        }
    }
    v.x = __float2bfloat16(f[0]);
    v.y = __float2bfloat16(f[1]);
    ((__nv_bfloat162*)g_wi_h)[idx] = v;
}

// ---------------- K3b: pi patches transposed (bf16 [b][d][l]), 2 l/thread ----------------
__global__ void k_patch_pit()
{
    int idx = blockIdx.x * 256 + threadIdx.x;    // < BATCH*DD*LL/2
    int l2 = idx & (LL / 2 - 1);
    int rest = idx / (LL / 2);
    int d = rest % DD;
    int bb = rest / DD;
    int ci = d / 49;
    int rc = d % 49;
    int r = rc / 7, c = rc % 7;
    int l0 = l2 * 2;
    int y = (l0 >> 6) * STR + r - PT;
    int x0 = (l0 & 63) * STR + c - PLW;
    const float* src = g_b2 + (size_t)(bb * CI + ci) * HH * WW;
    float f0 = 0.f, f1 = 0.f;
    if ((unsigned)y < HH) {
        if ((unsigned)x0 < WW)       f0 = src[y * WW + x0];
        if ((unsigned)(x0 + 4) < WW) f1 = src[y * WW + x0 + 4];
    }
    __nv_bfloat162 v;
    v.x = __float2bfloat16(f0);
    v.y = __float2bfloat16(f1);
    ((__nv_bfloat162*)g_pit_h)[idx] = v;
}

// ---------------- mma helpers ----------------
__device__ __forceinline__ void cpa16(void* dst, const void* src, bool pred)
{
    unsigned d = (unsigned)__cvta_generic_to_shared(dst);
    int sz = pred ? 16 : 0;
    asm volatile("cp.async.cg.shared.global [%0], [%1], 16, %2;\n"
                 :: "r"(d), "l"(src), "r"(sz));
}
__device__ __forceinline__ void ldsm_x4(uint32_t* r, const void* p)
{
    unsigned a = (unsigned)__cvta_generic_to_shared(p);
    asm volatile("ldmatrix.sync.aligned.m8n8.x4.shared.b16 {%0,%1,%2,%3}, [%4];"
                 : "=r"(r[0]), "=r"(r[1]), "=r"(r[2]), "=r"(r[3]) : "r"(a));
}
__device__ __forceinline__ void ldsm_x2(uint32_t* r, const void* p)
{
    unsigned a = (unsigned)__cvta_generic_to_shared(p);
    asm volatile("ldmatrix.sync.aligned.m8n8.x2.shared.b16 {%0,%1}, [%2];"
                 : "=r"(r[0]), "=r"(r[1]) : "r"(a));
}
__device__ __forceinline__ void mma_bf16(float* c, const uint32_t* a, const uint32_t* b)
{
    asm volatile("mma.sync.aligned.m16n8k16.row.col.f32.bf16.bf16.f32 "
                 "{%0,%1,%2,%3}, {%4,%5,%6,%7}, {%8,%9}, {%0,%1,%2,%3};"
                 : "+f"(c[0]), "+f"(c[1]), "+f"(c[2]), "+f"(c[3])
                 : "r"(a[0]), "r"(a[1]), "r"(a[2]), "r"(a[3]), "r"(b[0]), "r"(b[1]));
}

// ---------------- main bf16 mma GEMM, KT=64, 3-stage, 1 sync/iter ----------------
// op 0: z sel: wif/xif = relu(wi @ fcN_w^T + b)  M=8192 N=256 K=832 -> bf16
// op 2: score = wif @ xif^T (batch z)  M=4096 N=4096 K=256  -> fp16 g_attn
#define SROW 72                           // 64 K halves + 8 pad
#define NST  3
#define SMS  (128 * SROW)                 // halves per stage per matrix
#define GEMM_DSM (NST * SMS * 2 * 2)      // bytes (A + B) = 110592

__global__ __launch_bounds__(256, 2) void k_gemm3(int op,
                                                  const float* __restrict__ b1p,
                                                  const float* __restrict__ b2p)
{
    extern __shared__ __align__(16) char dsm[];
    __nv_bfloat16* smA = (__nv_bfloat16*)dsm;
    __nv_bfloat16* smB = (__nv_bfloat16*)(dsm + NST * SMS * 2);

    const __nv_bfloat16 *A, *B;
    __nv_bfloat16* Ch = nullptr;
    __half* Chf = nullptr;
    const float* bias = b1p;
    int KdPad, Nvalid, mode;   // mode 0=fc 1=score
    size_t z = blockIdx.z;
    if (op == 0) {
        A = g_wi_h; B = z ? g_w2h : g_w1h; Ch = z ? g_xif_h : g_wif_h;
        bias = z ? b2p : b1p;
        KdPad = DDP; Nvalid = DOUT; mode = 0;
    } else {
        A = g_wif_h + z * (size_t)LL * DOUTP; B = g_xif_h + z * (size_t)LL * DOUTP;
        Chf = g_attn + z * (size_t)LL * LL;
        KdPad = DOUTP; Nvalid = LL; mode = 1;
    }
    const int ldA = KdPad, ldB = KdPad;

    const int t = threadIdx.x;
    const int m0 = blockIdx.y * 128, n0 = blockIdx.x * 128;
    const int arow0 = t >> 3;        // 0..31
    const int aseg  = (t & 7) * 8;   // 0..56 halves

    const int wid = t >> 5, lane = t & 31;
    const int wm = (wid & 1) * 64, wn = (wid >> 1) * 32;
    const int grp = lane >> 2, q = lane & 3;
    const int lr = lane & 7, ls = lane >> 3;
    const int aoff = ((ls & 1) * 8 + lr) * SROW + (ls >> 1) * 8;
    const int boff = (lane & 7) * SROW + ((lane >> 3) & 1) * 8;

    float acc[4][4][4];
#pragma unroll
    for (int i = 0; i < 4; i++)
#pragma unroll
        for (int j = 0; j < 4; j++)
#pragma unroll
            for (int r = 0; r < 4; r++) acc[i][j][r] = 0.f;

#define LOAD_TILE(stg, k0_)                                                             \
    {                                                                                   \
        int k0v = (k0_);                                                                \
        __nv_bfloat16* sA = smA + (stg) * SMS;                                          \
        __nv_bfloat16* sB = smB + (stg) * SMS;                                          \
        _Pragma("unroll")                                                               \
        for (int j = 0; j < 4; j++) {                                                   \
            int row = arow0 + j * 32;                                                   \
            cpa16(&sA[row * SROW + aseg],                                               \
                  A + (size_t)(m0 + row) * ldA + k0v + aseg, true);                     \
        }                                                                               \
        _Pragma("unroll")                                                               \
        for (int j = 0; j < 4; j++) {                                                   \
            int row = arow0 + j * 32;                                                   \
            cpa16(&sB[row * SROW + aseg],                                               \
                  B + (size_t)(n0 + row) * ldB + k0v + aseg, (n0 + row) < Nvalid);      \
        }                                                                               \
        asm volatile("cp.async.commit_group;");                                         \
    }

    const int ktiles = KdPad / 64;
    LOAD_TILE(0, 0);
    if (ktiles > 1) LOAD_TILE(1, 64);

    for (int kt = 0; kt < ktiles; kt++) {
        const int s = kt % NST;
        if (kt + 1 < ktiles) asm volatile("cp.async.wait_group 1;");
        else                 asm volatile("cp.async.wait_group 0;");
        __syncthreads();
        if (kt + 2 < ktiles) LOAD_TILE((kt + 2) % NST, (kt + 2) * 64);

        const __nv_bfloat16* sA = smA + s * SMS;
        const __nv_bfloat16* sB = smB + s * SMS;
#pragma unroll
        for (int kk = 0; kk < 4; kk++) {
            uint32_t af[4][4], bfr[4][2];
#pragma unroll
            for (int mt = 0; mt < 4; mt++)
                ldsm_x4(af[mt], &sA[(wm + mt * 16) * SROW + kk * 16 + aoff]);
#pragma unroll
            for (int nt = 0; nt < 4; nt++)
                ldsm_x2(bfr[nt], &sB[(wn + nt * 8) * SROW + kk * 16 + boff]);
#pragma unroll
            for (int mt = 0; mt < 4; mt++)
#pragma unroll
                for (int nt = 0; nt < 4; nt++)
                    mma_bf16(acc[mt][nt], af[mt], bfr[nt]);
        }
    }
#undef LOAD_TILE

    // ---- epilogue ----
#pragma unroll
    for (int mt = 0; mt < 4; mt++) {
        int r0 = m0 + wm + mt * 16 + grp;
#pragma unroll
        for (int nt = 0; nt < 4; nt++) {
            int c0 = n0 + wn + nt * 8 + 2 * q;
            float v0 = acc[mt][nt][0], v1 = acc[mt][nt][1];
            float v2 = acc[mt][nt][2], v3 = acc[mt][nt][3];
            if (mode == 0) {
                if (c0 < DOUTP) {
                    float b0 = (c0 < DOUT) ? bias[c0] : 0.f;
                    float b1 = (c0 + 1 < DOUT) ? bias[c0 + 1] : 0.f;
                    v0 = fmaxf(v0 + b0, 0.f); v1 = fmaxf(v1 + b1, 0.f);
                    v2 = fmaxf(v2 + b0, 0.f); v3 = fmaxf(v3 + b1, 0.f);
                    __nv_bfloat162 w;
                    w.x = __float2bfloat16(c0 < DOUT ? v0 : 0.f);
                    w.y = __float2bfloat16(c0 + 1 < DOUT ? v1 : 0.f);
                    *(__nv_bfloat162*)(Ch + (size_t)r0 * DOUTP + c0) = w;
                    w.x = __float2bfloat16(c0 < DOUT ? v2 : 0.f);
                    w.y = __float2bfloat16(c0 + 1 < DOUT ? v3 : 0.f);
                    *(__nv_bfloat162*)(Ch + (size_t)(r0 + 8) * DOUTP + c0) = w;
                }
            } else {
                *(__half2*)(Chf + (size_t)r0 * LL + c0) = __floats2half2_rn(v0, v1);
                *(__half2*)(Chf + (size_t)(r0 + 8) * LL + c0) = __floats2half2_rn(v2, v3);
            }
        }
    }
}

// ---------------- agg GEMM: 128x64 tile (tail/wave-efficient) ----------------
// agg = attnh @ pit^T (batch z)  M=4096 N=784 K=4096 -> fp32 g_agg
#define SMSA (128 * SROW)
#define SMSB (64 * SROW)
#define AGG_DSM (NST * (SMSA + SMSB) * 2)     // 82944 bytes

__global__ __launch_bounds__(256, 2) void k_gemm_n64()
{
    extern __shared__ __align__(16) char dsm[];
    __nv_bfloat16* smA = (__nv_bfloat16*)dsm;
    __nv_bfloat16* smB = (__nv_bfloat16*)(dsm + NST * SMSA * 2);

    size_t z = blockIdx.z;
    const __nv_bfloat16* A = g_attnh + z * (size_t)LL * LL;
    const __nv_bfloat16* B = g_pit_h + z * (size_t)DD * LL;
    float* Cf = g_agg + z * (size_t)LL * DD;
    const int ldA = LL, ldB = LL, ldC = DD;

    const int t = threadIdx.x;
    const int m0 = blockIdx.y * 128, n0 = blockIdx.x * 64;
    const int arow0 = t >> 3;        // 0..31
    const int aseg  = (t & 7) * 8;

    const int wid = t >> 5, lane = t & 31;
    const int wm = (wid >> 1) * 32;  // 0,32,64,96
    const int wn = (wid & 1) * 32;   // 0,32
    const int grp = lane >> 2, q = lane & 3;
    const int lr = lane & 7, ls = lane >> 3;
    const int aoff = ((ls & 1) * 8 + lr) * SROW + (ls >> 1) * 8;
    const int boff = (lane & 7) * SROW + ((lane >> 3) & 1) * 8;

    float acc[2][4][4];
#pragma unroll
    for (int i = 0; i < 2; i++)
#pragma unroll
        for (int j = 0; j < 4; j++)
#pragma unroll
            for (int r = 0; r < 4; r++) acc[i][j][r] = 0.f;

#define LOAD_TILE_A(stg, k0_)                                                           \
    {                                                                                   \
        int k0v = (k0_);                                                                \
        __nv_bfloat16* sA = smA + (stg) * SMSA;                                         \
        __nv_bfloat16* sB = smB + (stg) * SMSB;                                         \
        _Pragma("unroll")                                                               \
        for (int j = 0; j < 4; j++) {                                                   \
            int row = arow0 + j * 32;                                                   \
            cpa16(&sA[row * SROW + aseg],                                               \
                  A + (size_t)(m0 + row) * ldA + k0v + aseg, true);                     \
        }                                                                               \
        _Pragma("unroll")                                                               \
        for (int j = 0; j < 2; j++) {                                                   \
            int row = arow0 + j * 32;                                                   \
            cpa16(&sB[row * SROW + aseg],                                               \
                  B + (size_t)(n0 + row) * ldB + k0v + aseg, (n0 + row) < DD);          \
        }                                                                               \
        asm volatile("cp.async.commit_group;");                                         \
    }

    const int ktiles = LL / 64;    // 64
    LOAD_TILE_A(0, 0);
    LOAD_TILE_A(1, 64);

    for (int kt = 0; kt < ktiles; kt++) {
        const int s = kt % NST;
        if (kt + 1 < ktiles) asm volatile("cp.async.wait_group 1;");
        else                 asm volatile("cp.async.wait_group 0;");
        __syncthreads();
        if (kt + 2 < ktiles) LOAD_TILE_A((kt + 2) % NST, (kt + 2) * 64);

        const __nv_bfloat16* sA = smA + s * SMSA;
        const __nv_bfloat16* sB = smB + s * SMSB;
#pragma unroll
        for (int kk = 0; kk < 4; kk++) {
            uint32_t af[2][4], bfr[4][2];
#pragma unroll
            for (int mt = 0; mt < 2; mt++)
                ldsm_x4(af[mt], &sA[(wm + mt * 16) * SROW + kk * 16 + aoff]);
#pragma unroll
            for (int nt = 0; nt < 4; nt++)
                ldsm_x2(bfr[nt], &sB[(wn + nt * 8) * SROW + kk * 16 + boff]);
#pragma unroll
            for (int mt = 0; mt < 2; mt++)
#pragma unroll
                for (int nt = 0; nt < 4; nt++)
                    mma_bf16(acc[mt][nt], af[mt], bfr[nt]);
        }
    }
#undef LOAD_TILE_A

    // ---- epilogue ----
#pragma unroll
    for (int mt = 0; mt < 2; mt++) {
        int r0 = m0 + wm + mt * 16 + grp;
#pragma unroll
        for (int nt = 0; nt < 4; nt++) {
            int c0 = n0 + wn + nt * 8 + 2 * q;
            float v0 = acc[mt][nt][0], v1 = acc[mt][nt][1];
            float v2 = acc[mt][nt][2], v3 = acc[mt][nt][3];
            if (c0 < DD) {
                Cf[(size_t)r0 * ldC + c0] = v0;
                Cf[(size_t)(r0 + 8) * ldC + c0] = v2;
            }
            if (c0 + 1 < DD) {
                Cf[(size_t)r0 * ldC + c0 + 1] = v1;
                Cf[(size_t)(r0 + 8) * ldC + c0 + 1] = v3;
            }
        }
    }
}

// ---------------- K5: masked softmax per row (fp16 in, bf16 out) ----------------
__global__ __launch_bounds__(256) void k_softmax()
{
    size_t roff = (size_t)blockIdx.x * LL;
    float th = g_thr[blockIdx.x];
    float bi = g_bias[blockIdx.x];
    int t = threadIdx.x;
    const __half2* src = (const __half2*)(g_attn + roff);

    float v[16];
    float lmax = -1e30f;
#pragma unroll
    for (int i = 0; i < 8; i++) {
        float2 f = __half22float2(src[t + i * 256]);
        v[2 * i] = f.x;
        v[2 * i + 1] = f.y;
        float g0 = (f.x >= th) ? 10.f * (f.x + bi) : 10.f * bi;
        float g1 = (f.y >= th) ? 10.f * (f.y + bi) : 10.f * bi;
        lmax = fmaxf(lmax, fmaxf(g0, g1));
    }
    __shared__ float mbuf[8], zbuf[8], sbuf[8];
    for (int o = 16; o; o >>= 1) lmax = fmaxf(lmax, __shfl_xor_sync(0xffffffffu, lmax, o));
    if ((t & 31) == 0) mbuf[t >> 5] = lmax;
    __syncthreads();
    float M = mbuf[0];
#pragma unroll
    for (int w = 1; w < 8; w++) M = fmaxf(M, mbuf[w]);

    float zp = 0.f, sp = 0.f;
#pragma unroll
    for (int i = 0; i < 16; i++) {
        bool mk = v[i] >= th;
        float gg = mk ? 10.f * (v[i] + bi) : 10.f * bi;
        float e = __expf(gg - M);
        zp += e;
        float em = mk ? e : 0.f;
        sp += em;
        v[i] = em;
    }
    for (int o = 16; o; o >>= 1) {
        zp += __shfl_xor_sync(0xffffffffu, zp, o);
        sp += __shfl_xor_sync(0xffffffffu, sp, o);
    }
    if ((t & 31) == 0) { zbuf[t >> 5] = zp; sbuf[t >> 5] = sp; }
    __syncthreads();
    float Z = 0.f, S = 0.f;
#pragma unroll
    for (int w = 0; w < 8; w++) { Z += zbuf[w]; S += sbuf[w]; }

    float inv = 1.f / (S + 1e-8f * Z);
    __nv_bfloat162* dst = (__nv_bfloat162*)(g_attnh + roff);
#pragma unroll
    for (int i = 0; i < 8; i++) {
        __nv_bfloat162 w;
        w.x = __float2bfloat16(v[2 * i] * inv);
        w.y = __float2bfloat16(v[2 * i + 1] * inv);
        dst[t + i * 256] = w;
    }
}

// ---------------- K7: fold + 1x1 conv + residual (f32x2 conv) ----------------
__global__ __launch_bounds__(256) void k_fold(float* __restrict__ out,
                                              const float* __restrict__ bin,
                                              const float* __restrict__ Ww,
                                              const float* __restrict__ Wb)
{
    __shared__ unsigned long long sW2[32 * CI];   // [co_pair][ci]
    __shared__ float sWb[CIN];
    int t = threadIdx.x;
    for (int i = t; i < 32 * CI; i += 256) {
        int p = i >> 4, ci = i & 15;
        sW2[i] = pack2(Ww[(2 * p) * CI + ci], Ww[(2 * p + 1) * CI + ci]);
    }
    if (t < CIN) sWb[t] = Wb[t];
    __syncthreads();

    int bz = blockIdx.z;
    int y = blockIdx.y * 16 + (t >> 4);
    int x = blockIdx.x * 16 + (t & 15);
    int yp = y + 1, xp = x + 1;

    int lh_lo = (yp >= 3) ? ((yp - 3) >> 2) : 0;
    int lh_hi = min(LHH - 1, yp >> 2);
    int lw_lo = (xp >= 3) ? ((xp - 3) >> 2) : 0;
    int lw_hi = min(LWW - 1, xp >> 2);

    float zacc[CI];
#pragma unroll
    for (int ci = 0; ci < CI; ci++) zacc[ci] = 0.f;

    for (int lh = lh_lo; lh <= lh_hi; lh++) {
        int r = yp - lh * 4;
        for (int lw = lw_lo; lw <= lw_hi; lw++) {
            int c = xp - lw * 4;
            const float* basep = g_agg + ((size_t)bz * LL + (lh * 64 + lw)) * DD + r * 7 + c;
#pragma unroll
            for (int ci = 0; ci < CI; ci++) zacc[ci] += basep[ci * 49];
        }
    }
    float cnt = (float)((lh_hi - lh_lo + 1) * (lw_hi - lw_lo + 1));
    float invc = 1.f / cnt;
    unsigned long long z2[CI];
#pragma unroll
    for (int ci = 0; ci < CI; ci++) {
        float zv = zacc[ci] * invc;
        z2[ci] = pack2(zv, zv);
    }

    size_t pix = (size_t)y * WW + x;
    const float* bp = bin + (size_t)bz * CIN * HH * WW + pix;
    float* op = out + (size_t)bz * CIN * HH * WW + pix;
#pragma unroll 8
    for (int p = 0; p < 32; p++) {
        unsigned long long a = 0ull;
#pragma unroll
        for (int ci = 0; ci < CI; ci++) fma2(a, sW2[p * CI + ci], z2[ci]);
        float s0, s1;
        unpack2(s0, s1, a);
        int co0 = 2 * p, co1 = 2 * p + 1;
        op[(size_t)co0 * HH * WW] = bp[(size_t)co0 * HH * WW] + s0 + sWb[co0];
        op[(size_t)co1 * HH * WW] = bp[(size_t)co1 * HH * WW] + s1 + sWb[co1];
    }
}

// ---------------- launch ----------------
extern "C" void kernel_launch(void* const* d_in, const int* in_sizes, int n_in,
                              void* d_out, int out_size)
{
    const float* b     = (const float*)d_in[0];
    const float* g_w   = (const float*)d_in[1];
    const float* g_bv  = (const float*)d_in[2];
    const float* th_w  = (const float*)d_in[3];
    const float* th_b  = (const float*)d_in[4];
    const float* W_w   = (const float*)d_in[5];
    const float* W_b   = (const float*)d_in[6];
    const float* fc1w  = (const float*)d_in[7];
    const float* fc1b  = (const float*)d_in[8];
    const float* fc2w  = (const float*)d_in[9];
    const float* fc2b  = (const float*)d_in[10];
    const float* thrw  = (const float*)d_in[11];
    const float* thrb  = (const float*)d_in[12];
    const float* bisw  = (const float*)d_in[13];
    const float* bisb  = (const float*)d_in[14];
    float* out = (float*)d_out;

    cudaFuncSetAttribute(k_gemm3, cudaFuncAttributeMaxDynamicSharedMemorySize, GEMM_DSM);
    cudaFuncSetAttribute(k_gemm_n64, cudaFuncAttributeMaxDynamicSharedMemorySize, AGG_DSM);

    // fc weights -> bf16 (padded K)
    k_cvt_w<<<(2 * DOUT * DDP + 255) / 256, 256>>>(fc1w, fc2w);
    // b1 (3x3) + b2 (1x1), exact fp32 (packed f32x2)
    k_conv<<<512, 256>>>(b, g_w, g_bv, th_w, th_b);
    // thr / bias maps (4 patches per block)
    k_thrbias<<<BATCH * LL / 4, 256>>>(b, thrw, thrb, bisw, bisb);
    // patches
    k_patch_wi<<<BATCH * LL * (DDP / 2) / 256, 256>>>();
    k_patch_pit<<<BATCH * DD * (LL / 2) / 256, 256>>>();
    // fc1 + fc2 fused (z dim)
    k_gemm3<<<dim3(2, 64, 2), 256, GEMM_DSM>>>(0, fc1b, fc2b);
    // score = wif @ xif^T -> fp16
    k_gemm3<<<dim3(32, 32, 2), 256, GEMM_DSM>>>(2, nullptr, nullptr);
    // masked softmax (fp16 -> bf16 attn)
    k_softmax<<<BATCH * LL, 256>>>();
    // agg = attnh @ pit^T -> fp32 (128x64 tiles)
    k_gemm_n64<<<dim3(13, 32, 2), 256, AGG_DSM>>>();
    // fold + 1x1 conv + residual
    k_fold<<<dim3(16, 16, BATCH), 256>>>(out, b, W_w, W_b);
}

// round 15
// speedup vs baseline: 1.0745x; 1.0745x over previous
#include <cuda_runtime.h>
#include <cuda_bf16.h>
#include <cuda_fp16.h>
#include <cstdint>
#include <cstddef>

// ---------------- problem constants ----------------
#define BATCH 2
#define CIN   64
#define HH    256
#define WW    256
#define CI    16
#define KS    7
#define STR   4
#define PT    1
#define PLW   1
#define LHH   64
#define LWW   64
#define LL    4096          // LHH*LWW
#define DD    784           // CI*KS*KS
#define DDP   832           // DD padded to mult of 64 (fc K)
#define DOUT  196
#define DOUTP 256           // DOUT padded to mult of 64

// ---------------- device scratch ----------------
__device__ __align__(16) float g_b1 [BATCH*CI*HH*WW];                 // 8 MB
__device__ __align__(16) float g_b2 [BATCH*CI*HH*WW];                 // 8 MB
__device__ __align__(16) __nv_bfloat16 g_wi_h [BATCH*LL*DDP];         // [b][l][832] pad->0
__device__ __align__(16) __nv_bfloat16 g_pit_h[BATCH*DD*LL];          // [b][d][l]
__device__ __align__(16) __nv_bfloat16 g_w1h[DOUT*DDP];
__device__ __align__(16) __nv_bfloat16 g_w2h[DOUT*DDP];
__device__ __align__(16) __nv_bfloat16 g_wif_h[BATCH*LL*DOUTP];
__device__ __align__(16) __nv_bfloat16 g_xif_h[BATCH*LL*DOUTP];
__device__ __align__(16) float g_thr [BATCH*LL];
__device__ __align__(16) float g_bias[BATCH*LL];
__device__ __align__(16) __half g_attn[(size_t)BATCH*LL*LL];          // 67 MB fp16 scores
__device__ __align__(16) __nv_bfloat16 g_attnh[(size_t)BATCH*LL*LL];  // 67 MB bf16 attn
__device__ __align__(16) float g_agg[BATCH*LL*DD];                    // 25.7 MB

// ---------------- packed f32x2 helpers ----------------
__device__ __forceinline__ void fma2(unsigned long long& a, unsigned long long w,
                                     unsigned long long v)
{
    asm("fma.rn.f32x2 %0, %1, %2, %0;" : "+l"(a) : "l"(w), "l"(v));
}
__device__ __forceinline__ unsigned long long pack2(float x, float y)
{
    unsigned long long r;
    asm("mov.b64 %0, {%1, %2};" : "=l"(r) : "f"(x), "f"(y));
    return r;
}
__device__ __forceinline__ void unpack2(float& x, float& y, unsigned long long a)
{
    asm("mov.b64 {%0, %1}, %2;" : "=f"(x), "=f"(y) : "l"(a));
}

// ---------------- K0: fc weights fp32 -> bf16 (padded) ----------------
__global__ void k_cvt_w(const float* __restrict__ w1, const float* __restrict__ w2)
{
    int idx = blockIdx.x * 256 + threadIdx.x;
    if (idx >= 2 * DOUT * DDP) return;
    int zz = idx / (DOUT * DDP);
    int r = (idx / DDP) % DOUT;
    int c = idx % DDP;
    const float* w = zz ? w2 : w1;
    __nv_bfloat16* o = zz ? g_w2h : g_w1h;
    float v = (c < DD) ? w[r * DD + c] : 0.f;
    o[idx - zz * DOUT * DDP] = __float2bfloat16(v);
}

// ---------------- K1: conv3x3 (b1) + conv1x1 (b2), exact fp32, f32x2 packed ----------------
__global__ __launch_bounds__(256) void k_conv(const float* __restrict__ bin,
                                              const float* __restrict__ gw,
                                              const float* __restrict__ gb,
                                              const float* __restrict__ tw,
                                              const float* __restrict__ tb)
{
    __shared__ unsigned long long sGw2[CIN * 9 * 8];   // [(ci*9+tap)*8+p] = (w[2p], w[2p+1])
    __shared__ unsigned long long sTw2[CIN * 8];       // [ci*8+p]
    __shared__ float sGb[CI], sTb[CI];
    int t = threadIdx.x;
    for (int i = t; i < CIN * 9 * 8; i += 256) {
        int ci = i / 72;
        int tap = (i / 8) % 9;
        int p = i & 7;
        sGw2[i] = pack2(gw[((2 * p) * CIN + ci) * 9 + tap],
                        gw[((2 * p + 1) * CIN + ci) * 9 + tap]);
    }
    for (int i = t; i < CIN * 8; i += 256) {
        int ci = i / 8;
        int p = i & 7;
        sTw2[i] = pack2(tw[(2 * p) * CIN + ci], tw[(2 * p + 1) * CIN + ci]);
    }
    if (t < CI) { sGb[t] = gb[t]; sTb[t] = tb[t]; }
    __syncthreads();

    int idx = blockIdx.x * 256 + t;
    int x = idx & 255;
    int y = (idx >> 8) & 255;
    int bb = idx >> 16;

    unsigned long long a1p[8], a2p[8];
#pragma unroll
    for (int p = 0; p < 8; p++) { a1p[p] = 0ull; a2p[p] = 0ull; }

    bool ym = y > 0, yP = y < HH - 1, xm = x > 0, xP = x < WW - 1;
    const float* base = bin + ((size_t)bb * CIN * HH + y) * WW + x;

    for (int ci = 0; ci < CIN; ci++) {
        const float* p = base + (size_t)ci * HH * WW;
        float v4 = p[0];
        float v0 = (ym && xm) ? p[-WW - 1] : 0.f;
        float v1 = ym ? p[-WW] : 0.f;
        float v2 = (ym && xP) ? p[-WW + 1] : 0.f;
        float v3 = xm ? p[-1] : 0.f;
        float v5 = xP ? p[1] : 0.f;
        float v6 = (yP && xm) ? p[WW - 1] : 0.f;
        float v7 = yP ? p[WW] : 0.f;
        float v8 = (yP && xP) ? p[WW + 1] : 0.f;
        unsigned long long vv[9];
        vv[0] = pack2(v0, v0); vv[1] = pack2(v1, v1); vv[2] = pack2(v2, v2);
        vv[3] = pack2(v3, v3); vv[4] = pack2(v4, v4); vv[5] = pack2(v5, v5);
        vv[6] = pack2(v6, v6); vv[7] = pack2(v7, v7); vv[8] = pack2(v8, v8);
        const unsigned long long* wg = sGw2 + ci * 72;
#pragma unroll
        for (int pp = 0; pp < 8; pp++) {
#pragma unroll
            for (int tap = 0; tap < 9; tap++)
                fma2(a1p[pp], wg[tap * 8 + pp], vv[tap]);
            fma2(a2p[pp], sTw2[ci * 8 + pp], vv[4]);
        }
    }
#pragma unroll
    for (int pp = 0; pp < 8; pp++) {
        float x0, x1, y0, y1;
        unpack2(x0, x1, a1p[pp]);
        unpack2(y0, y1, a2p[pp]);
        int co0 = 2 * pp, co1 = 2 * pp + 1;
        size_t off0 = ((size_t)(bb * CI + co0) * HH + y) * WW + x;
        size_t off1 = ((size_t)(bb * CI + co1) * HH + y) * WW + x;
        g_b1[off0] = x0 + sGb[co0];
        g_b1[off1] = x1 + sGb[co1];
        g_b2[off0] = y0 + sTb[co0];
        g_b2[off1] = y1 + sTb[co1];
    }
}

// ---------------- K2: thr / bias conv7x7 stride4 (4 patches / block) ----------------
__global__ __launch_bounds__(256) void k_thrbias(const float* __restrict__ bin,
                          const float* __restrict__ thw, const float* __restrict__ thb,
                          const float* __restrict__ biw, const float* __restrict__ bib)
{
    int t = threadIdx.x;
    int g = t >> 6;                      // patch group 0..3
    int ci = t & 63;
    int blk = blockIdx.x * 4 + g;        // b*LL + l
    int bb = blk >> 12;
    int l  = blk & (LL - 1);
    int lh = l >> 6, lw = l & 63;
    const float* src = bin + (size_t)(bb * CIN + ci) * HH * WW;
    float s1 = 0.f, s2 = 0.f;
    for (int r = 0; r < KS; r++) {
        int y = lh * STR + r - PT;
        if ((unsigned)y < HH) {
            for (int c = 0; c < KS; c++) {
                int x = lw * STR + c - PLW;
                if ((unsigned)x < WW) {
                    float v = src[y * WW + x];
                    s1 += v * thw[ci * 49 + r * 7 + c];
                    s2 += v * biw[ci * 49 + r * 7 + c];
                }
            }
        }
    }
    for (int o = 16; o; o >>= 1) {
        s1 += __shfl_xor_sync(0xffffffffu, s1, o);
        s2 += __shfl_xor_sync(0xffffffffu, s2, o);
    }
    __shared__ float r1[8], r2[8];
    if ((t & 31) == 0) { r1[t >> 5] = s1; r2[t >> 5] = s2; }
    __syncthreads();
    if ((t & 63) == 0) {
        int w0 = t >> 5;                 // = g*2
        g_thr [blk] = r1[w0] + r1[w0 + 1] + thb[0];
        g_bias[blk] = r2[w0] + r2[w0 + 1] + bib[0];
    }
}

// ---------------- K3a: wi patches (bf16 [b][l][832]), 2 elems/thread ----------------
__global__ void k_patch_wi()
{
    int idx = blockIdx.x * 256 + threadIdx.x;    // < BATCH*LL*DDP/2
    int d2 = idx % (DDP / 2);
    int bl = idx / (DDP / 2);
    int l = bl & (LL - 1);
    int bb = bl >> 12;
    int yb = (l >> 6) * STR - PT;
    int xb = (l & 63) * STR - PLW;
    __nv_bfloat162 v;
    float f[2] = {0.f, 0.f};
#pragma unroll
    for (int j = 0; j < 2; j++) {
        int d = d2 * 2 + j;
        if (d < DD) {
            int ci = d / 49;
            int rc = d % 49;
            int r = rc / 7, c = rc % 7;
            int y = yb + r, x = xb + c;
            if ((unsigned)y < HH && (unsigned)x < WW)
                f[j] = g_b1[((size_t)(bb * CI + ci) * HH + y) * WW + x];
        }
    }
    v.x = __float2bfloat16(f[0]);
    v.y = __float2bfloat16(f[1]);
    ((__nv_bfloat162*)g_wi_h)[idx] = v;
}

// ---------------- K3b: pi patches transposed (bf16 [b][d][l]), 2 l/thread ----------------
__global__ void k_patch_pit()
{
    int idx = blockIdx.x * 256 + threadIdx.x;    // < BATCH*DD*LL/2
    int l2 = idx & (LL / 2 - 1);
    int rest = idx / (LL / 2);
    int d = rest % DD;
    int bb = rest / DD;
    int ci = d / 49;
    int rc = d % 49;
    int r = rc / 7, c = rc % 7;
    int l0 = l2 * 2;
    int y = (l0 >> 6) * STR + r - PT;
    int x0 = (l0 & 63) * STR + c - PLW;
    const float* src = g_b2 + (size_t)(bb * CI + ci) * HH * WW;
    float f0 = 0.f, f1 = 0.f;
    if ((unsigned)y < HH) {
        if ((unsigned)x0 < WW)       f0 = src[y * WW + x0];
        if ((unsigned)(x0 + 4) < WW) f1 = src[y * WW + x0 + 4];
    }
    __nv_bfloat162 v;
    v.x = __float2bfloat16(f0);
    v.y = __float2bfloat16(f1);
    ((__nv_bfloat162*)g_pit_h)[idx] = v;
}

// ---------------- mma helpers ----------------
__device__ __forceinline__ void cpa16(void* dst, const void* src, bool pred)
{
    unsigned d = (unsigned)__cvta_generic_to_shared(dst);
    int sz = pred ? 16 : 0;
    asm volatile("cp.async.cg.shared.global [%0], [%1], 16, %2;\n"
                 :: "r"(d), "l"(src), "r"(sz));
}
__device__ __forceinline__ void ldsm_x4(uint32_t* r, const void* p)
{
    unsigned a = (unsigned)__cvta_generic_to_shared(p);
    asm volatile("ldmatrix.sync.aligned.m8n8.x4.shared.b16 {%0,%1,%2,%3}, [%4];"
                 : "=r"(r[0]), "=r"(r[1]), "=r"(r[2]), "=r"(r[3]) : "r"(a));
}
__device__ __forceinline__ void ldsm_x4_2(uint32_t* r0, uint32_t* r1, const void* p)
{
    unsigned a = (unsigned)__cvta_generic_to_shared(p);
    asm volatile("ldmatrix.sync.aligned.m8n8.x4.shared.b16 {%0,%1,%2,%3}, [%4];"
                 : "=r"(r0[0]), "=r"(r0[1]), "=r"(r1[0]), "=r"(r1[1]) : "r"(a));
}
__device__ __forceinline__ void mma_bf16(float* c, const uint32_t* a, const uint32_t* b)
{
    asm volatile("mma.sync.aligned.m16n8k16.row.col.f32.bf16.bf16.f32 "
                 "{%0,%1,%2,%3}, {%4,%5,%6,%7}, {%8,%9}, {%0,%1,%2,%3};"
                 : "+f"(c[0]), "+f"(c[1]), "+f"(c[2]), "+f"(c[3])
                 : "r"(a[0]), "r"(a[1]), "r"(a[2]), "r"(a[3]), "r"(b[0]), "r"(b[1]));
}

// ---------------- main bf16 mma GEMM, KT=64, 3-stage, 1 sync/iter ----------------
// op 0: z sel: wif/xif = relu(wi @ fcN_w^T + b)  M=8192 N=256 K=832 -> bf16
// op 2: score = wif @ xif^T (batch z)  M=4096 N=4096 K=256  -> fp16 g_attn
// op 3: agg   = attnh @ pit^T (batch z) M=4096 N=784 K=4096 -> fp32 g_agg
#define SROW 72                           // 64 K halves + 8 pad
#define NST  3
#define SMS  (128 * SROW)                 // halves per stage per matrix
#define GEMM_DSM (NST * SMS * 2 * 2)      // bytes (A + B) = 110592

__global__ __launch_bounds__(256, 2) void k_gemm3(int op,
                                                  const float* __restrict__ b1p,
                                                  const float* __restrict__ b2p)
{
    extern __shared__ __align__(16) char dsm[];
    __nv_bfloat16* smA = (__nv_bfloat16*)dsm;
    __nv_bfloat16* smB = (__nv_bfloat16*)(dsm + NST * SMS * 2);

    const __nv_bfloat16 *A, *B;
    float* Cf = nullptr;
    __nv_bfloat16* Ch = nullptr;
    __half* Chf = nullptr;
    const float* bias = b1p;
    int KdPad, Nvalid, mode;   // mode 0=fc 1=score 2=agg
    size_t z = blockIdx.z;
    if (op == 0) {
        A = g_wi_h; B = z ? g_w2h : g_w1h; Ch = z ? g_xif_h : g_wif_h;
        bias = z ? b2p : b1p;
        KdPad = DDP; Nvalid = DOUT; mode = 0;
    } else if (op == 2) {
        A = g_wif_h + z * (size_t)LL * DOUTP; B = g_xif_h + z * (size_t)LL * DOUTP;
        Chf = g_attn + z * (size_t)LL * LL;
        KdPad = DOUTP; Nvalid = LL; mode = 1;
    } else {
        A = g_attnh + z * (size_t)LL * LL; B = g_pit_h + z * (size_t)DD * LL;
        Cf = g_agg + z * (size_t)LL * DD;
        KdPad = LL; Nvalid = DD; mode = 2;
    }
    const int ldA = KdPad, ldB = KdPad;
    const int ldC = (mode == 0) ? DOUTP : (mode == 1 ? LL : DD);

    const int t = threadIdx.x;
    const int m0 = blockIdx.y * 128, n0 = blockIdx.x * 128;
    const int arow0 = t >> 3;        // 0..31
    const int aseg  = (t & 7) * 8;   // 0..56 halves

    const int wid = t >> 5, lane = t & 31;
    const int wm = (wid & 1) * 64, wn = (wid >> 1) * 32;
    const int grp = lane >> 2, q = lane & 3;
    const int lr = lane & 7, ls = lane >> 3;
    const int aoff = ((ls & 1) * 8 + lr) * SROW + (ls >> 1) * 8;
    // B x4: mats 0,1 = col-block np*16 (+0 rows), k-segs 0/8; mats 2,3 = +8 rows
    const int b4off = ((ls >> 1) * 8 + lr) * SROW + (ls & 1) * 8;

    float acc[4][4][4];
#pragma unroll
    for (int i = 0; i < 4; i++)
#pragma unroll
        for (int j = 0; j < 4; j++)
#pragma unroll
            for (int r = 0; r < 4; r++) acc[i][j][r] = 0.f;

#define LOAD_TILE(stg, k0_)                                                             \
    {                                                                                   \
        int k0v = (k0_);                                                                \
        __nv_bfloat16* sA = smA + (stg) * SMS;                                          \
        __nv_bfloat16* sB = smB + (stg) * SMS;                                          \
        _Pragma("unroll")                                                               \
        for (int j = 0; j < 4; j++) {                                                   \
            int row = arow0 + j * 32;                                                   \
            cpa16(&sA[row * SROW + aseg],                                               \
                  A + (size_t)(m0 + row) * ldA + k0v + aseg, true);                     \
        }                                                                               \
        _Pragma("unroll")                                                               \
        for (int j = 0; j < 4; j++) {                                                   \
            int row = arow0 + j * 32;                                                   \
            cpa16(&sB[row * SROW + aseg],                                               \
                  B + (size_t)(n0 + row) * ldB + k0v + aseg, (n0 + row) < Nvalid);      \
        }                                                                               \
        asm volatile("cp.async.commit_group;");                                         \
    }

    const int ktiles = KdPad / 64;
    LOAD_TILE(0, 0);
    if (ktiles > 1) LOAD_TILE(1, 64);

    for (int kt = 0; kt < ktiles; kt++) {
        const int s = kt % NST;
        if (kt + 1 < ktiles) asm volatile("cp.async.wait_group 1;");
        else                 asm volatile("cp.async.wait_group 0;");
        __syncthreads();
        if (kt + 2 < ktiles) LOAD_TILE((kt + 2) % NST, (kt + 2) * 64);

        const __nv_bfloat16* sA = smA + s * SMS;
        const __nv_bfloat16* sB = smB + s * SMS;
#pragma unroll
        for (int kk = 0; kk < 4; kk++) {
            uint32_t af[4][4], bfr[4][2];
#pragma unroll
            for (int mt = 0; mt < 4; mt++)
                ldsm_x4(af[mt], &sA[(wm + mt * 16) * SROW + kk * 16 + aoff]);
#pragma unroll
            for (int np = 0; np < 2; np++)
                ldsm_x4_2(bfr[2 * np], bfr[2 * np + 1],
                          &sB[(wn + np * 16) * SROW + kk * 16 + b4off]);
#pragma unroll
            for (int mt = 0; mt < 4; mt++)
#pragma unroll
                for (int nt = 0; nt < 4; nt++)
                    mma_bf16(acc[mt][nt], af[mt], bfr[nt]);
        }
    }
#undef LOAD_TILE

    // ---- epilogue ----
#pragma unroll
    for (int mt = 0; mt < 4; mt++) {
        int r0 = m0 + wm + mt * 16 + grp;
#pragma unroll
        for (int nt = 0; nt < 4; nt++) {
            int c0 = n0 + wn + nt * 8 + 2 * q;
            float v0 = acc[mt][nt][0], v1 = acc[mt][nt][1];
            float v2 = acc[mt][nt][2], v3 = acc[mt][nt][3];
            if (mode == 0) {
                if (c0 < DOUTP) {
                    float b0 = (c0 < DOUT) ? bias[c0] : 0.f;
                    float b1 = (c0 + 1 < DOUT) ? bias[c0 + 1] : 0.f;
                    v0 = fmaxf(v0 + b0, 0.f); v1 = fmaxf(v1 + b1, 0.f);
                    v2 = fmaxf(v2 + b0, 0.f); v3 = fmaxf(v3 + b1, 0.f);
                    __nv_bfloat162 w;
                    w.x = __float2bfloat16(c0 < DOUT ? v0 : 0.f);
                    w.y = __float2bfloat16(c0 + 1 < DOUT ? v1 : 0.f);
                    *(__nv_bfloat162*)(Ch + (size_t)r0 * DOUTP + c0) = w;
                    w.x = __float2bfloat16(c0 < DOUT ? v2 : 0.f);
                    w.y = __float2bfloat16(c0 + 1 < DOUT ? v3 : 0.f);
                    *(__nv_bfloat162*)(Ch + (size_t)(r0 + 8) * DOUTP + c0) = w;
                }
            } else if (mode == 1) {
                *(__half2*)(Chf + (size_t)r0 * LL + c0) = __floats2half2_rn(v0, v1);
                *(__half2*)(Chf + (size_t)(r0 + 8) * LL + c0) = __floats2half2_rn(v2, v3);
            } else {
                if (c0 < Nvalid) {
                    Cf[(size_t)r0 * ldC + c0] = v0;
                    Cf[(size_t)(r0 + 8) * ldC + c0] = v2;
                }
                if (c0 + 1 < Nvalid) {
                    Cf[(size_t)r0 * ldC + c0 + 1] = v1;
                    Cf[(size_t)(r0 + 8) * ldC + c0 + 1] = v3;
                }
            }
        }
    }
}

// ---------------- K5: masked softmax per row (fp16 in, bf16 out) ----------------
__global__ __launch_bounds__(256) void k_softmax()
{
    size_t roff = (size_t)blockIdx.x * LL;
    float th = g_thr[blockIdx.x];
    float bi = g_bias[blockIdx.x];
    int t = threadIdx.x;
    const __half2* src = (const __half2*)(g_attn + roff);

    float v[16];
    float lmax = -1e30f;
#pragma unroll
    for (int i = 0; i < 8; i++) {
        float2 f = __half22float2(src[t + i * 256]);
        v[2 * i] = f.x;
        v[2 * i + 1] = f.y;
        float g0 = (f.x >= th) ? 10.f * (f.x + bi) : 10.f * bi;
        float g1 = (f.y >= th) ? 10.f * (f.y + bi) : 10.f * bi;
        lmax = fmaxf(lmax, fmaxf(g0, g1));
    }
    __shared__ float mbuf[8], zbuf[8], sbuf[8];
    for (int o = 16; o; o >>= 1) lmax = fmaxf(lmax, __shfl_xor_sync(0xffffffffu, lmax, o));
    if ((t & 31) == 0) mbuf[t >> 5] = lmax;
    __syncthreads();
    float M = mbuf[0];
#pragma unroll
    for (int w = 1; w < 8; w++) M = fmaxf(M, mbuf[w]);

    float zp = 0.f, sp = 0.f;
#pragma unroll
    for (int i = 0; i < 16; i++) {
        bool mk = v[i] >= th;
        float gg = mk ? 10.f * (v[i] + bi) : 10.f * bi;
        float e = __expf(gg - M);
        zp += e;
        float em = mk ? e : 0.f;
        sp += em;
        v[i] = em;
    }
    for (int o = 16; o; o >>= 1) {
        zp += __shfl_xor_sync(0xffffffffu, zp, o);
        sp += __shfl_xor_sync(0xffffffffu, sp, o);
    }
    if ((t & 31) == 0) { zbuf[t >> 5] = zp; sbuf[t >> 5] = sp; }
    __syncthreads();
    float Z = 0.f, S = 0.f;
#pragma unroll
    for (int w = 0; w < 8; w++) { Z += zbuf[w]; S += sbuf[w]; }

    float inv = 1.f / (S + 1e-8f * Z);
    __nv_bfloat162* dst = (__nv_bfloat162*)(g_attnh + roff);
#pragma unroll
    for (int i = 0; i < 8; i++) {
        __nv_bfloat162 w;
        w.x = __float2bfloat16(v[2 * i] * inv);
        w.y = __float2bfloat16(v[2 * i + 1] * inv);
        dst[t + i * 256] = w;
    }
}

// ---------------- K7: fold + 1x1 conv + residual (f32x2 conv) ----------------
__global__ __launch_bounds__(256) void k_fold(float* __restrict__ out,
                                              const float* __restrict__ bin,
                                              const float* __restrict__ Ww,
                                              const float* __restrict__ Wb)
{
    __shared__ unsigned long long sW2[32 * CI];   // [co_pair][ci]
    __shared__ float sWb[CIN];
    int t = threadIdx.x;
    for (int i = t; i < 32 * CI; i += 256) {
        int p = i >> 4, ci = i & 15;
        sW2[i] = pack2(Ww[(2 * p) * CI + ci], Ww[(2 * p + 1) * CI + ci]);
    }
    if (t < CIN) sWb[t] = Wb[t];
    __syncthreads();

    int bz = blockIdx.z;
    int y = blockIdx.y * 16 + (t >> 4);
    int x = blockIdx.x * 16 + (t & 15);
    int yp = y + 1, xp = x + 1;

    int lh_lo = (yp >= 3) ? ((yp - 3) >> 2) : 0;
    int lh_hi = min(LHH - 1, yp >> 2);
    int lw_lo = (xp >= 3) ? ((xp - 3) >> 2) : 0;
    int lw_hi = min(LWW - 1, xp >> 2);

    float zacc[CI];
#pragma unroll
    for (int ci = 0; ci < CI; ci++) zacc[ci] = 0.f;

    for (int lh = lh_lo; lh <= lh_hi; lh++) {
        int r = yp - lh * 4;
        for (int lw = lw_lo; lw <= lw_hi; lw++) {
            int c = xp - lw * 4;
            const float* basep = g_agg + ((size_t)bz * LL + (lh * 64 + lw)) * DD + r * 7 + c;
#pragma unroll
            for (int ci = 0; ci < CI; ci++) zacc[ci] += basep[ci * 49];
        }
    }
    float cnt = (float)((lh_hi - lh_lo + 1) * (lw_hi - lw_lo + 1));
    float invc = 1.f / cnt;
    unsigned long long z2[CI];
#pragma unroll
    for (int ci = 0; ci < CI; ci++) {
        float zv = zacc[ci] * invc;
        z2[ci] = pack2(zv, zv);
    }

    size_t pix = (size_t)y * WW + x;
    const float* bp = bin + (size_t)bz * CIN * HH * WW + pix;
    float* op = out + (size_t)bz * CIN * HH * WW + pix;
#pragma unroll 8
    for (int p = 0; p < 32; p++) {
        unsigned long long a = 0ull;
#pragma unroll
        for (int ci = 0; ci < CI; ci++) fma2(a, sW2[p * CI + ci], z2[ci]);
        float s0, s1;
        unpack2(s0, s1, a);
        int co0 = 2 * p, co1 = 2 * p + 1;
        op[(size_t)co0 * HH * WW] = bp[(size_t)co0 * HH * WW] + s0 + sWb[co0];
        op[(size_t)co1 * HH * WW] = bp[(size_t)co1 * HH * WW] + s1 + sWb[co1];
    }
}

// ---------------- launch ----------------
extern "C" void kernel_launch(void* const* d_in, const int* in_sizes, int n_in,
                              void* d_out, int out_size)
{
    const float* b     = (const float*)d_in[0];
    const float* g_w   = (const float*)d_in[1];
    const float* g_bv  = (const float*)d_in[2];
    const float* th_w  = (const float*)d_in[3];
    const float* th_b  = (const float*)d_in[4];
    const float* W_w   = (const float*)d_in[5];
    const float* W_b   = (const float*)d_in[6];
    const float* fc1w  = (const float*)d_in[7];
    const float* fc1b  = (const float*)d_in[8];
    const float* fc2w  = (const float*)d_in[9];
    const float* fc2b  = (const float*)d_in[10];
    const float* thrw  = (const float*)d_in[11];
    const float* thrb  = (const float*)d_in[12];
    const float* bisw  = (const float*)d_in[13];
    const float* bisb  = (const float*)d_in[14];
    float* out = (float*)d_out;

    cudaFuncSetAttribute(k_gemm3, cudaFuncAttributeMaxDynamicSharedMemorySize, GEMM_DSM);

    // fc weights -> bf16 (padded K)
    k_cvt_w<<<(2 * DOUT * DDP + 255) / 256, 256>>>(fc1w, fc2w);
    // b1 (3x3) + b2 (1x1), exact fp32 (packed f32x2)
    k_conv<<<512, 256>>>(b, g_w, g_bv, th_w, th_b);
    // thr / bias maps (4 patches per block)
    k_thrbias<<<BATCH * LL / 4, 256>>>(b, thrw, thrb, bisw, bisb);
    // patches
    k_patch_wi<<<BATCH * LL * (DDP / 2) / 256, 256>>>();
    k_patch_pit<<<BATCH * DD * (LL / 2) / 256, 256>>>();
    // fc1 + fc2 fused (z dim)
    k_gemm3<<<dim3(2, 64, 2), 256, GEMM_DSM>>>(0, fc1b, fc2b);
    // score = wif @ xif^T -> fp16
    k_gemm3<<<dim3(32, 32, 2), 256, GEMM_DSM>>>(2, nullptr, nullptr);
    // masked softmax (fp16 -> bf16 attn)
    k_softmax<<<BATCH * LL, 256>>>();
    // agg = attnh @ pit^T -> fp32 (128x128 tiles, reverted)
    k_gemm3<<<dim3(7, 32, 2), 256, GEMM_DSM>>>(3, nullptr, nullptr);
    // fold + 1x1 conv + residual
    k_fold<<<dim3(16, 16, BATCH), 256>>>(out, b, W_w, W_b);
}

// round 16
// speedup vs baseline: 1.0902x; 1.0146x over previous
#include <cuda_runtime.h>
#include <cuda_bf16.h>
#include <cuda_fp16.h>
#include <cstdint>
#include <cstddef>

// ---------------- problem constants ----------------
#define BATCH 2
#define CIN   64
#define HH    256
#define WW    256
#define CI    16
#define KS    7
#define STR   4
#define PT    1
#define PLW   1
#define LHH   64
#define LWW   64
#define LL    4096          // LHH*LWW
#define DD    784           // CI*KS*KS
#define DDP   832           // DD padded to mult of 64 (fc K)
#define DOUT  196
#define DOUTP 224           // DOUT padded to mult of 32 (score K, 7x32)

// ---------------- device scratch ----------------
__device__ __align__(16) float g_b1 [BATCH*CI*HH*WW];                 // 8 MB
__device__ __align__(16) float g_b2 [BATCH*CI*HH*WW];                 // 8 MB
__device__ __align__(16) __nv_bfloat16 g_wi_h [BATCH*LL*DDP];         // [b][l][832] pad->0
__device__ __align__(16) __nv_bfloat16 g_pit_h[BATCH*DD*LL];          // [b][d][l]
__device__ __align__(16) __nv_bfloat16 g_w1h[DOUT*DDP];
__device__ __align__(16) __nv_bfloat16 g_w2h[DOUT*DDP];
__device__ __align__(16) __nv_bfloat16 g_wif_h[BATCH*LL*DOUTP];
__device__ __align__(16) __nv_bfloat16 g_xif_h[BATCH*LL*DOUTP];
__device__ __align__(16) float g_thr [BATCH*LL];
__device__ __align__(16) float g_bias[BATCH*LL];
__device__ __align__(16) __half g_attn[(size_t)BATCH*LL*LL];          // 67 MB fp16 scores
__device__ __align__(16) __nv_bfloat16 g_attnh[(size_t)BATCH*LL*LL];  // 67 MB bf16 attn
__device__ __align__(16) __nv_bfloat16 g_agg[BATCH*LL*DD];            // 12.8 MB bf16

// ---------------- packed f32x2 helpers ----------------
__device__ __forceinline__ void fma2(unsigned long long& a, unsigned long long w,
                                     unsigned long long v)
{
    asm("fma.rn.f32x2 %0, %1, %2, %0;" : "+l"(a) : "l"(w), "l"(v));
}
__device__ __forceinline__ unsigned long long pack2(float x, float y)
{
    unsigned long long r;
    asm("mov.b64 %0, {%1, %2};" : "=l"(r) : "f"(x), "f"(y));
    return r;
}
__device__ __forceinline__ void unpack2(float& x, float& y, unsigned long long a)
{
    asm("mov.b64 {%0, %1}, %2;" : "=f"(x), "=f"(y) : "l"(a));
}

// ---------------- K0: fc weights fp32 -> bf16 (padded) ----------------
__global__ void k_cvt_w(const float* __restrict__ w1, const float* __restrict__ w2)
{
    int idx = blockIdx.x * 256 + threadIdx.x;
    if (idx >= 2 * DOUT * DDP) return;
    int zz = idx / (DOUT * DDP);
    int r = (idx / DDP) % DOUT;
    int c = idx % DDP;
    const float* w = zz ? w2 : w1;
    __nv_bfloat16* o = zz ? g_w2h : g_w1h;
    float v = (c < DD) ? w[r * DD + c] : 0.f;
    o[idx - zz * DOUT * DDP] = __float2bfloat16(v);
}

// ---------------- K1: conv3x3 (b1) + conv1x1 (b2), exact fp32, f32x2 packed ----------------
__global__ __launch_bounds__(256) void k_conv(const float* __restrict__ bin,
                                              const float* __restrict__ gw,
                                              const float* __restrict__ gb,
                                              const float* __restrict__ tw,
                                              const float* __restrict__ tb)
{
    __shared__ unsigned long long sGw2[CIN * 9 * 8];
    __shared__ unsigned long long sTw2[CIN * 8];
    __shared__ float sGb[CI], sTb[CI];
    int t = threadIdx.x;
    for (int i = t; i < CIN * 9 * 8; i += 256) {
        int ci = i / 72;
        int tap = (i / 8) % 9;
        int p = i & 7;
        sGw2[i] = pack2(gw[((2 * p) * CIN + ci) * 9 + tap],
                        gw[((2 * p + 1) * CIN + ci) * 9 + tap]);
    }
    for (int i = t; i < CIN * 8; i += 256) {
        int ci = i / 8;
        int p = i & 7;
        sTw2[i] = pack2(tw[(2 * p) * CIN + ci], tw[(2 * p + 1) * CIN + ci]);
    }
    if (t < CI) { sGb[t] = gb[t]; sTb[t] = tb[t]; }
    __syncthreads();

    int idx = blockIdx.x * 256 + t;
    int x = idx & 255;
    int y = (idx >> 8) & 255;
    int bb = idx >> 16;

    unsigned long long a1p[8], a2p[8];
#pragma unroll
    for (int p = 0; p < 8; p++) { a1p[p] = 0ull; a2p[p] = 0ull; }

    bool ym = y > 0, yP = y < HH - 1, xm = x > 0, xP = x < WW - 1;
    const float* base = bin + ((size_t)bb * CIN * HH + y) * WW + x;

    for (int ci = 0; ci < CIN; ci++) {
        const float* p = base + (size_t)ci * HH * WW;
        float v4 = p[0];
        float v0 = (ym && xm) ? p[-WW - 1] : 0.f;
        float v1 = ym ? p[-WW] : 0.f;
        float v2 = (ym && xP) ? p[-WW + 1] : 0.f;
        float v3 = xm ? p[-1] : 0.f;
        float v5 = xP ? p[1] : 0.f;
        float v6 = (yP && xm) ? p[WW - 1] : 0.f;
        float v7 = yP ? p[WW] : 0.f;
        float v8 = (yP && xP) ? p[WW + 1] : 0.f;
        unsigned long long vv[9];
        vv[0] = pack2(v0, v0); vv[1] = pack2(v1, v1); vv[2] = pack2(v2, v2);
        vv[3] = pack2(v3, v3); vv[4] = pack2(v4, v4); vv[5] = pack2(v5, v5);
        vv[6] = pack2(v6, v6); vv[7] = pack2(v7, v7); vv[8] = pack2(v8, v8);
        const unsigned long long* wg = sGw2 + ci * 72;
#pragma unroll
        for (int pp = 0; pp < 8; pp++) {
#pragma unroll
            for (int tap = 0; tap < 9; tap++)
                fma2(a1p[pp], wg[tap * 8 + pp], vv[tap]);
            fma2(a2p[pp], sTw2[ci * 8 + pp], vv[4]);
        }
    }
#pragma unroll
    for (int pp = 0; pp < 8; pp++) {
        float x0, x1, y0, y1;
        unpack2(x0, x1, a1p[pp]);
        unpack2(y0, y1, a2p[pp]);
        int co0 = 2 * pp, co1 = 2 * pp + 1;
        size_t off0 = ((size_t)(bb * CI + co0) * HH + y) * WW + x;
        size_t off1 = ((size_t)(bb * CI + co1) * HH + y) * WW + x;
        g_b1[off0] = x0 + sGb[co0];
        g_b1[off1] = x1 + sGb[co1];
        g_b2[off0] = y0 + sTb[co0];
        g_b2[off1] = y1 + sTb[co1];
    }
}

// ---------------- K2: thr / bias conv7x7 stride4 (4 patches / block) ----------------
__global__ __launch_bounds__(256) void k_thrbias(const float* __restrict__ bin,
                          const float* __restrict__ thw, const float* __restrict__ thb,
                          const float* __restrict__ biw, const float* __restrict__ bib)
{
    int t = threadIdx.x;
    int g = t >> 6;
    int ci = t & 63;
    int blk = blockIdx.x * 4 + g;
    int bb = blk >> 12;
    int l  = blk & (LL - 1);
    int lh = l >> 6, lw = l & 63;
    const float* src = bin + (size_t)(bb * CIN + ci) * HH * WW;
    float s1 = 0.f, s2 = 0.f;
    for (int r = 0; r < KS; r++) {
        int y = lh * STR + r - PT;
        if ((unsigned)y < HH) {
            for (int c = 0; c < KS; c++) {
                int x = lw * STR + c - PLW;
                if ((unsigned)x < WW) {
                    float v = src[y * WW + x];
                    s1 += v * thw[ci * 49 + r * 7 + c];
                    s2 += v * biw[ci * 49 + r * 7 + c];
                }
            }
        }
    }
    for (int o = 16; o; o >>= 1) {
        s1 += __shfl_xor_sync(0xffffffffu, s1, o);
        s2 += __shfl_xor_sync(0xffffffffu, s2, o);
    }
    __shared__ float r1[8], r2[8];
    if ((t & 31) == 0) { r1[t >> 5] = s1; r2[t >> 5] = s2; }
    __syncthreads();
    if ((t & 63) == 0) {
        int w0 = t >> 5;
        g_thr [blk] = r1[w0] + r1[w0 + 1] + thb[0];
        g_bias[blk] = r2[w0] + r2[w0 + 1] + bib[0];
    }
}

// ---------------- K3a: wi patches (bf16 [b][l][832]), 2 elems/thread ----------------
__global__ void k_patch_wi()
{
    int idx = blockIdx.x * 256 + threadIdx.x;
    int d2 = idx % (DDP / 2);
    int bl = idx / (DDP / 2);
    int l = bl & (LL - 1);
    int bb = bl >> 12;
    int yb = (l >> 6) * STR - PT;
    int xb = (l & 63) * STR - PLW;
    __nv_bfloat162 v;
    float f[2] = {0.f, 0.f};
#pragma unroll
    for (int j = 0; j < 2; j++) {
        int d = d2 * 2 + j;
        if (d < DD) {
            int ci = d / 49;
            int rc = d % 49;
            int r = rc / 7, c = rc % 7;
            int y = yb + r, x = xb + c;
            if ((unsigned)y < HH && (unsigned)x < WW)
                f[j] = g_b1[((size_t)(bb * CI + ci) * HH + y) * WW + x];
        }
    }
    v.x = __float2bfloat16(f[0]);
    v.y = __float2bfloat16(f[1]);
    ((__nv_bfloat162*)g_wi_h)[idx] = v;
}

// ---------------- K3b: pi patches transposed (bf16 [b][d][l]), 2 l/thread ----------------
__global__ void k_patch_pit()
{
    int idx = blockIdx.x * 256 + threadIdx.x;
    int l2 = idx & (LL / 2 - 1);
    int rest = idx / (LL / 2);
    int d = rest % DD;
    int bb = rest / DD;
    int ci = d / 49;
    int rc = d % 49;
    int r = rc / 7, c = rc % 7;
    int l0 = l2 * 2;
    int y = (l0 >> 6) * STR + r - PT;
    int x0 = (l0 & 63) * STR + c - PLW;
    const float* src = g_b2 + (size_t)(bb * CI + ci) * HH * WW;
    float f0 = 0.f, f1 = 0.f;
    if ((unsigned)y < HH) {
        if ((unsigned)x0 < WW)       f0 = src[y * WW + x0];
        if ((unsigned)(x0 + 4) < WW) f1 = src[y * WW + x0 + 4];
    }
    __nv_bfloat162 v;
    v.x = __float2bfloat16(f0);
    v.y = __float2bfloat16(f1);
    ((__nv_bfloat162*)g_pit_h)[idx] = v;
}

// ---------------- mma helpers ----------------
__device__ __forceinline__ void cpa16(void* dst, const void* src, bool pred)
{
    unsigned d = (unsigned)__cvta_generic_to_shared(dst);
    int sz = pred ? 16 : 0;
    asm volatile("cp.async.cg.shared.global [%0], [%1], 16, %2;\n"
                 :: "r"(d), "l"(src), "r"(sz));
}
__device__ __forceinline__ void ldsm_x4(uint32_t* r, const void* p)
{
    unsigned a = (unsigned)__cvta_generic_to_shared(p);
    asm volatile("ldmatrix.sync.aligned.m8n8.x4.shared.b16 {%0,%1,%2,%3}, [%4];"
                 : "=r"(r[0]), "=r"(r[1]), "=r"(r[2]), "=r"(r[3]) : "r"(a));
}
__device__ __forceinline__ void ldsm_x4_2(uint32_t* r0, uint32_t* r1, const void* p)
{
    unsigned a = (unsigned)__cvta_generic_to_shared(p);
    asm volatile("ldmatrix.sync.aligned.m8n8.x4.shared.b16 {%0,%1,%2,%3}, [%4];"
                 : "=r"(r0[0]), "=r"(r0[1]), "=r"(r1[0]), "=r"(r1[1]) : "r"(a));
}
__device__ __forceinline__ void mma_bf16(float* c, const uint32_t* a, const uint32_t* b)
{
    asm volatile("mma.sync.aligned.m16n8k16.row.col.f32.bf16.bf16.f32 "
                 "{%0,%1,%2,%3}, {%4,%5,%6,%7}, {%8,%9}, {%0,%1,%2,%3};"
                 : "+f"(c[0]), "+f"(c[1]), "+f"(c[2]), "+f"(c[3])
                 : "r"(a[0]), "r"(a[1]), "r"(a[2]), "r"(a[3]), "r"(b[0]), "r"(b[1]));
}

// ---------------- fc + agg GEMM, KT=64, 3-stage, 1 sync/iter ----------------
// op 0: z sel: wif/xif = relu(wi @ fcN_w^T + b)  M=8192 N=224 K=832 -> bf16
// op 3: agg   = attnh @ pit^T (batch z) M=4096 N=784 K=4096 -> bf16 g_agg
#define SROW 72                           // 64 K halves + 8 pad
#define NST  3
#define SMS  (128 * SROW)
#define GEMM_DSM (NST * SMS * 2 * 2)      // 110592 bytes

__global__ __launch_bounds__(256, 2) void k_gemm3(int op,
                                                  const float* __restrict__ b1p,
                                                  const float* __restrict__ b2p)
{
    extern __shared__ __align__(16) char dsm[];
    __nv_bfloat16* smA = (__nv_bfloat16*)dsm;
    __nv_bfloat16* smB = (__nv_bfloat16*)(dsm + NST * SMS * 2);

    const __nv_bfloat16 *A, *B;
    __nv_bfloat16* Ch;
    const float* bias = b1p;
    int KdPad, Nvalid, mode;   // mode 0=fc 2=agg
    size_t z = blockIdx.z;
    if (op == 0) {
        A = g_wi_h; B = z ? g_w2h : g_w1h; Ch = z ? g_xif_h : g_wif_h;
        bias = z ? b2p : b1p;
        KdPad = DDP; Nvalid = DOUT; mode = 0;
    } else {
        A = g_attnh + z * (size_t)LL * LL; B = g_pit_h + z * (size_t)DD * LL;
        Ch = g_agg + z * (size_t)LL * DD;
        KdPad = LL; Nvalid = DD; mode = 2;
    }
    const int ldA = KdPad, ldB = KdPad;
    const int ldC = (mode == 0) ? DOUTP : DD;

    const int t = threadIdx.x;
    const int m0 = blockIdx.y * 128, n0 = blockIdx.x * 128;
    const int arow0 = t >> 3;
    const int aseg  = (t & 7) * 8;

    const int wid = t >> 5, lane = t & 31;
    const int wm = (wid & 1) * 64, wn = (wid >> 1) * 32;
    const int grp = lane >> 2, q = lane & 3;
    const int lr = lane & 7, ls = lane >> 3;
    const int aoff = ((ls & 1) * 8 + lr) * SROW + (ls >> 1) * 8;
    const int b4off = ((ls >> 1) * 8 + lr) * SROW + (ls & 1) * 8;

    float acc[4][4][4];
#pragma unroll
    for (int i = 0; i < 4; i++)
#pragma unroll
        for (int j = 0; j < 4; j++)
#pragma unroll
            for (int r = 0; r < 4; r++) acc[i][j][r] = 0.f;

#define LOAD_TILE(stg, k0_)                                                             \
    {                                                                                   \
        int k0v = (k0_);                                                                \
        __nv_bfloat16* sA = smA + (stg) * SMS;                                          \
        __nv_bfloat16* sB = smB + (stg) * SMS;                                          \
        _Pragma("unroll")                                                               \
        for (int j = 0; j < 4; j++) {                                                   \
            int row = arow0 + j * 32;                                                   \
            cpa16(&sA[row * SROW + aseg],                                               \
                  A + (size_t)(m0 + row) * ldA + k0v + aseg, true);                     \
        }                                                                               \
        _Pragma("unroll")                                                               \
        for (int j = 0; j < 4; j++) {                                                   \
            int row = arow0 + j * 32;                                                   \
            cpa16(&sB[row * SROW + aseg],                                               \
                  B + (size_t)(n0 + row) * ldB + k0v + aseg, (n0 + row) < Nvalid);      \
        }                                                                               \
        asm volatile("cp.async.commit_group;");                                         \
    }

    const int ktiles = KdPad / 64;
    LOAD_TILE(0, 0);
    if (ktiles > 1) LOAD_TILE(1, 64);

    for (int kt = 0; kt < ktiles; kt++) {
        const int s = kt % NST;
        if (kt + 1 < ktiles) asm volatile("cp.async.wait_group 1;");
        else                 asm volatile("cp.async.wait_group 0;");
        __syncthreads();
        if (kt + 2 < ktiles) LOAD_TILE((kt + 2) % NST, (kt + 2) * 64);

        const __nv_bfloat16* sA = smA + s * SMS;
        const __nv_bfloat16* sB = smB + s * SMS;
#pragma unroll
        for (int kk = 0; kk < 4; kk++) {
            uint32_t af[4][4], bfr[4][2];
#pragma unroll
            for (int mt = 0; mt < 4; mt++)
                ldsm_x4(af[mt], &sA[(wm + mt * 16) * SROW + kk * 16 + aoff]);
#pragma unroll
            for (int np = 0; np < 2; np++)
                ldsm_x4_2(bfr[2 * np], bfr[2 * np + 1],
                          &sB[(wn + np * 16) * SROW + kk * 16 + b4off]);
#pragma unroll
            for (int mt = 0; mt < 4; mt++)
#pragma unroll
                for (int nt = 0; nt < 4; nt++)
                    mma_bf16(acc[mt][nt], af[mt], bfr[nt]);
        }
    }
#undef LOAD_TILE

    // ---- epilogue ----
#pragma unroll
    for (int mt = 0; mt < 4; mt++) {
        int r0 = m0 + wm + mt * 16 + grp;
#pragma unroll
        for (int nt = 0; nt < 4; nt++) {
            int c0 = n0 + wn + nt * 8 + 2 * q;
            float v0 = acc[mt][nt][0], v1 = acc[mt][nt][1];
            float v2 = acc[mt][nt][2], v3 = acc[mt][nt][3];
            if (mode == 0) {
                if (c0 < DOUTP) {     // DOUTP even, c0 even -> covers the pair
                    float b0 = (c0 < DOUT) ? bias[c0] : 0.f;
                    float b1 = (c0 + 1 < DOUT) ? bias[c0 + 1] : 0.f;
                    v0 = fmaxf(v0 + b0, 0.f); v1 = fmaxf(v1 + b1, 0.f);
                    v2 = fmaxf(v2 + b0, 0.f); v3 = fmaxf(v3 + b1, 0.f);
                    __nv_bfloat162 w;
                    w.x = __float2bfloat16(c0 < DOUT ? v0 : 0.f);
                    w.y = __float2bfloat16(c0 + 1 < DOUT ? v1 : 0.f);
                    *(__nv_bfloat162*)(Ch + (size_t)r0 * DOUTP + c0) = w;
                    w.x = __float2bfloat16(c0 < DOUT ? v2 : 0.f);
                    w.y = __float2bfloat16(c0 + 1 < DOUT ? v3 : 0.f);
                    *(__nv_bfloat162*)(Ch + (size_t)(r0 + 8) * DOUTP + c0) = w;
                }
            } else {
                if (c0 < DD) {        // DD even, c0 even -> covers the pair
                    __nv_bfloat162 w;
                    w.x = __float2bfloat16(v0);
                    w.y = __float2bfloat16(v1);
                    *(__nv_bfloat162*)(Ch + (size_t)r0 * DD + c0) = w;
                    w.x = __float2bfloat16(v2);
                    w.y = __float2bfloat16(v3);
                    *(__nv_bfloat162*)(Ch + (size_t)(r0 + 8) * DD + c0) = w;
                }
            }
        }
    }
}

// ---------------- score GEMM: KT=32 (K=224 exact), fp16 out ----------------
// score = wif @ xif^T (batch z)  M=4096 N=4096 K=224 -> fp16 g_attn
#define SROW_S 40
#define SMS_S  (128 * SROW_S)
#define SC_DSM (NST * SMS_S * 2 * 2)      // 61440 bytes

__global__ __launch_bounds__(256, 2) void k_gemm_s()
{
    extern __shared__ __align__(16) char dsm[];
    __nv_bfloat16* smA = (__nv_bfloat16*)dsm;
    __nv_bfloat16* smB = (__nv_bfloat16*)(dsm + NST * SMS_S * 2);

    size_t z = blockIdx.z;
    const __nv_bfloat16* A = g_wif_h + z * (size_t)LL * DOUTP;
    const __nv_bfloat16* B = g_xif_h + z * (size_t)LL * DOUTP;
    __half* C = g_attn + z * (size_t)LL * LL;

    const int t = threadIdx.x;
    const int m0 = blockIdx.y * 128, n0 = blockIdx.x * 128;
    const int arow0 = t >> 2;        // 0..63
    const int aseg  = (t & 3) * 8;   // 0,8,16,24

    const int wid = t >> 5, lane = t & 31;
    const int wm = (wid & 1) * 64, wn = (wid >> 1) * 32;
    const int grp = lane >> 2, q = lane & 3;
    const int lr = lane & 7, ls = lane >> 3;
    const int aoff = ((ls & 1) * 8 + lr) * SROW_S + (ls >> 1) * 8;
    const int b4off = ((ls >> 1) * 8 + lr) * SROW_S + (ls & 1) * 8;

    float acc[4][4][4];
#pragma unroll
    for (int i = 0; i < 4; i++)
#pragma unroll
        for (int j = 0; j < 4; j++)
#pragma unroll
            for (int r = 0; r < 4; r++) acc[i][j][r] = 0.f;

#define LOAD_TS(stg, k0_)                                                               \
    {                                                                                   \
        int k0v = (k0_);                                                                \
        __nv_bfloat16* sA = smA + (stg) * SMS_S;                                        \
        __nv_bfloat16* sB = smB + (stg) * SMS_S;                                        \
        _Pragma("unroll")                                                               \
        for (int j = 0; j < 2; j++) {                                                   \
            int row = arow0 + j * 64;                                                   \
            cpa16(&sA[row * SROW_S + aseg],                                             \
                  A + (size_t)(m0 + row) * DOUTP + k0v + aseg, true);                   \
            cpa16(&sB[row * SROW_S + aseg],                                             \
                  B + (size_t)(n0 + row) * DOUTP + k0v + aseg, true);                   \
        }                                                                               \
        asm volatile("cp.async.commit_group;");                                         \
    }

    const int ktiles = DOUTP / 32;   // 7
    LOAD_TS(0, 0);
    LOAD_TS(1, 32);

    for (int kt = 0; kt < ktiles; kt++) {
        const int s = kt % NST;
        if (kt + 1 < ktiles) asm volatile("cp.async.wait_group 1;");
        else                 asm volatile("cp.async.wait_group 0;");
        __syncthreads();
        if (kt + 2 < ktiles) LOAD_TS((kt + 2) % NST, (kt + 2) * 32);

        const __nv_bfloat16* sA = smA + s * SMS_S;
        const __nv_bfloat16* sB = smB + s * SMS_S;
#pragma unroll
        for (int kk = 0; kk < 2; kk++) {
            uint32_t af[4][4], bfr[4][2];
#pragma unroll
            for (int mt = 0; mt < 4; mt++)
                ldsm_x4(af[mt], &sA[(wm + mt * 16) * SROW_S + kk * 16 + aoff]);
#pragma unroll
            for (int np = 0; np < 2; np++)
                ldsm_x4_2(bfr[2 * np], bfr[2 * np + 1],
                          &sB[(wn + np * 16) * SROW_S + kk * 16 + b4off]);
#pragma unroll
            for (int mt = 0; mt < 4; mt++)
#pragma unroll
                for (int nt = 0; nt < 4; nt++)
                    mma_bf16(acc[mt][nt], af[mt], bfr[nt]);
        }
    }
#undef LOAD_TS

#pragma unroll
    for (int mt = 0; mt < 4; mt++) {
        int r0 = m0 + wm + mt * 16 + grp;
#pragma unroll
        for (int nt = 0; nt < 4; nt++) {
            int c0 = n0 + wn + nt * 8 + 2 * q;
            *(__half2*)(C + (size_t)r0 * LL + c0) =
                __floats2half2_rn(acc[mt][nt][0], acc[mt][nt][1]);
            *(__half2*)(C + (size_t)(r0 + 8) * LL + c0) =
                __floats2half2_rn(acc[mt][nt][2], acc[mt][nt][3]);
        }
    }
}

// ---------------- K5: masked softmax per row (fp16 in, bf16 out) ----------------
__global__ __launch_bounds__(256) void k_softmax()
{
    size_t roff = (size_t)blockIdx.x * LL;
    float th = g_thr[blockIdx.x];
    float bi = g_bias[blockIdx.x];
    int t = threadIdx.x;
    const __half2* src = (const __half2*)(g_attn + roff);

    float v[16];
    float lmax = -1e30f;
#pragma unroll
    for (int i = 0; i < 8; i++) {
        float2 f = __half22float2(src[t + i * 256]);
        v[2 * i] = f.x;
        v[2 * i + 1] = f.y;
        float g0 = (f.x >= th) ? 10.f * (f.x + bi) : 10.f * bi;
        float g1 = (f.y >= th) ? 10.f * (f.y + bi) : 10.f * bi;
        lmax = fmaxf(lmax, fmaxf(g0, g1));
    }
    __shared__ float mbuf[8], zbuf[8], sbuf[8];
    for (int o = 16; o; o >>= 1) lmax = fmaxf(lmax, __shfl_xor_sync(0xffffffffu, lmax, o));
    if ((t & 31) == 0) mbuf[t >> 5] = lmax;
    __syncthreads();
    float M = mbuf[0];
#pragma unroll
    for (int w = 1; w < 8; w++) M = fmaxf(M, mbuf[w]);

    float zp = 0.f, sp = 0.f;
#pragma unroll
    for (int i = 0; i < 16; i++) {
        bool mk = v[i] >= th;
        float gg = mk ? 10.f * (v[i] + bi) : 10.f * bi;
        float e = __expf(gg - M);
        zp += e;
        float em = mk ? e : 0.f;
        sp += em;
        v[i] = em;
    }
    for (int o = 16; o; o >>= 1) {
        zp += __shfl_xor_sync(0xffffffffu, zp, o);
        sp += __shfl_xor_sync(0xffffffffu, sp, o);
    }
    if ((t & 31) == 0) { zbuf[t >> 5] = zp; sbuf[t >> 5] = sp; }
    __syncthreads();
    float Z = 0.f, S = 0.f;
#pragma unroll
    for (int w = 0; w < 8; w++) { Z += zbuf[w]; S += sbuf[w]; }

    float inv = 1.f / (S + 1e-8f * Z);
    __nv_bfloat162* dst = (__nv_bfloat162*)(g_attnh + roff);
#pragma unroll
    for (int i = 0; i < 8; i++) {
        __nv_bfloat162 w;
        w.x = __float2bfloat16(v[2 * i] * inv);
        w.y = __float2bfloat16(v[2 * i + 1] * inv);
        dst[t + i * 256] = w;
    }
}

// ---------------- K7: fold + 1x1 conv + residual (f32x2 conv, bf16 agg in) ----------------
__global__ __launch_bounds__(256) void k_fold(float* __restrict__ out,
                                              const float* __restrict__ bin,
                                              const float* __restrict__ Ww,
                                              const float* __restrict__ Wb)
{
    __shared__ unsigned long long sW2[32 * CI];
    __shared__ float sWb[CIN];
    int t = threadIdx.x;
    for (int i = t; i < 32 * CI; i += 256) {
        int p = i >> 4, ci = i & 15;
        sW2[i] = pack2(Ww[(2 * p) * CI + ci], Ww[(2 * p + 1) * CI + ci]);
    }
    if (t < CIN) sWb[t] = Wb[t];
    __syncthreads();

    int bz = blockIdx.z;
    int y = blockIdx.y * 16 + (t >> 4);
    int x = blockIdx.x * 16 + (t & 15);
    int yp = y + 1, xp = x + 1;

    int lh_lo = (yp >= 3) ? ((yp - 3) >> 2) : 0;
    int lh_hi = min(LHH - 1, yp >> 2);
    int lw_lo = (xp >= 3) ? ((xp - 3) >> 2) : 0;
    int lw_hi = min(LWW - 1, xp >> 2);

    float zacc[CI];
#pragma unroll
    for (int ci = 0; ci < CI; ci++) zacc[ci] = 0.f;

    for (int lh = lh_lo; lh <= lh_hi; lh++) {
        int r = yp - lh * 4;
        for (int lw = lw_lo; lw <= lw_hi; lw++) {
            int c = xp - lw * 4;
            const __nv_bfloat16* basep =
                g_agg + ((size_t)bz * LL + (lh * 64 + lw)) * DD + r * 7 + c;
#pragma unroll
            for (int ci = 0; ci < CI; ci++)
                zacc[ci] += __bfloat162float(basep[ci * 49]);
        }
    }
    float cnt = (float)((lh_hi - lh_lo + 1) * (lw_hi - lw_lo + 1));
    float invc = 1.f / cnt;
    unsigned long long z2[CI];
#pragma unroll
    for (int ci = 0; ci < CI; ci++) {
        float zv = zacc[ci] * invc;
        z2[ci] = pack2(zv, zv);
    }

    size_t pix = (size_t)y * WW + x;
    const float* bp = bin + (size_t)bz * CIN * HH * WW + pix;
    float* op = out + (size_t)bz * CIN * HH * WW + pix;
#pragma unroll 8
    for (int p = 0; p < 32; p++) {
        unsigned long long a = 0ull;
#pragma unroll
        for (int ci = 0; ci < CI; ci++) fma2(a, sW2[p * CI + ci], z2[ci]);
        float s0, s1;
        unpack2(s0, s1, a);
        int co0 = 2 * p, co1 = 2 * p + 1;
        op[(size_t)co0 * HH * WW] = bp[(size_t)co0 * HH * WW] + s0 + sWb[co0];
        op[(size_t)co1 * HH * WW] = bp[(size_t)co1 * HH * WW] + s1 + sWb[co1];
    }
}

// ---------------- launch ----------------
extern "C" void kernel_launch(void* const* d_in, const int* in_sizes, int n_in,
                              void* d_out, int out_size)
{
    const float* b     = (const float*)d_in[0];
    const float* g_w   = (const float*)d_in[1];
    const float* g_bv  = (const float*)d_in[2];
    const float* th_w  = (const float*)d_in[3];
    const float* th_b  = (const float*)d_in[4];
    const float* W_w   = (const float*)d_in[5];
    const float* W_b   = (const float*)d_in[6];
    const float* fc1w  = (const float*)d_in[7];
    const float* fc1b  = (const float*)d_in[8];
    const float* fc2w  = (const float*)d_in[9];
    const float* fc2b  = (const float*)d_in[10];
    const float* thrw  = (const float*)d_in[11];
    const float* thrb  = (const float*)d_in[12];
    const float* bisw  = (const float*)d_in[13];
    const float* bisb  = (const float*)d_in[14];
    float* out = (float*)d_out;

    cudaFuncSetAttribute(k_gemm3, cudaFuncAttributeMaxDynamicSharedMemorySize, GEMM_DSM);
    cudaFuncSetAttribute(k_gemm_s, cudaFuncAttributeMaxDynamicSharedMemorySize, SC_DSM);

    // fc weights -> bf16 (padded K)
    k_cvt_w<<<(2 * DOUT * DDP + 255) / 256, 256>>>(fc1w, fc2w);
    // b1 (3x3) + b2 (1x1), exact fp32 (packed f32x2)
    k_conv<<<512, 256>>>(b, g_w, g_bv, th_w, th_b);
    // thr / bias maps
    k_thrbias<<<BATCH * LL / 4, 256>>>(b, thrw, thrb, bisw, bisb);
    // patches
    k_patch_wi<<<BATCH * LL * (DDP / 2) / 256, 256>>>();
    k_patch_pit<<<BATCH * DD * (LL / 2) / 256, 256>>>();
    // fc1 + fc2 fused (z dim)
    k_gemm3<<<dim3(2, 64, 2), 256, GEMM_DSM>>>(0, fc1b, fc2b);
    // score = wif @ xif^T -> fp16 (KT=32, K=224 exact)
    k_gemm_s<<<dim3(32, 32, 2), 256, SC_DSM>>>();
    // masked softmax (fp16 -> bf16 attn)
    k_softmax<<<BATCH * LL, 256>>>();
    // agg = attnh @ pit^T -> bf16
    k_gemm3<<<dim3(7, 32, 2), 256, GEMM_DSM>>>(3, nullptr, nullptr);
    // fold + 1x1 conv + residual
    k_fold<<<dim3(16, 16, BATCH), 256>>>(out, b, W_w, W_b);
}